// round 17
// baseline (speedup 1.0000x reference)
#include <cuda_runtime.h>
#include <cuda_bf16.h>
#include <cstdint>
#include <math.h>

// ---------------- problem constants ----------------
#define BATCH   8
#define NSEQ    1024
#define DIMM    512
#define DH      64
#define HEADS   8
#define QKVDIM  1536            // 3*DIM
#define BH      (BATCH*HEADS)   // 64
#define MROWS   (BATCH*NSEQ)    // 8192
#define ATT_SCALE 0.125f        // 64^-0.5

typedef unsigned long long u64;

__device__ __forceinline__ uint32_t smem_u32(const void* p) {
    uint32_t a;
    asm("{ .reg .u64 t; cvta.to.shared.u64 t, %1; cvt.u32.u64 %0, t; }"
        : "=r"(a) : "l"(p));
    return a;
}

// ---------------- warp-MMA primitives (baseline PTX, compute_103-safe) -----
__device__ __forceinline__ void ldsm_x4(uint32_t (&r)[4], uint32_t addr) {
    asm volatile("ldmatrix.sync.aligned.m8n8.x4.shared.b16 {%0,%1,%2,%3}, [%4];"
        : "=r"(r[0]), "=r"(r[1]), "=r"(r[2]), "=r"(r[3]) : "r"(addr));
}
__device__ __forceinline__ void mma_bf16(float (&d)[4], const uint32_t (&a)[4],
                                         uint32_t b0, uint32_t b1) {
    asm volatile(
        "mma.sync.aligned.m16n8k16.row.col.f32.bf16.bf16.f32 "
        "{%0,%1,%2,%3}, {%4,%5,%6,%7}, {%8,%9}, {%0,%1,%2,%3};"
        : "+f"(d[0]), "+f"(d[1]), "+f"(d[2]), "+f"(d[3])
        : "r"(a[0]), "r"(a[1]), "r"(a[2]), "r"(a[3]), "r"(b0), "r"(b1));
}
#define CP_ASYNC16(dst, src) \
    asm volatile("cp.async.cg.shared.global [%0], [%1], 16;" :: "r"(dst), "l"(src))
#define CP_COMMIT() asm volatile("cp.async.commit_group;")
#define CP_WAIT1()  asm volatile("cp.async.wait_group 1;")
#define CP_WAIT0()  asm volatile("cp.async.wait_group 0;")

// ---------------- scratch (no allocation allowed) ----------------
__device__ float g_qkv [MROWS*QKVDIM];   // [b*N+n][1536]  (q|k|v), includes b_qkv
__device__ float g_qsum[BH*NSEQ];
__device__ float g_ksum[BH*NSEQ];
__device__ float g_g1  [BH*NSEQ];
__device__ float g_g2  [BH*NSEQ];
// bf16 split operand buffers (hi + lo = fp32 value)
__device__ __align__(16) __nv_bfloat16 g_xh [MROWS*DIMM],  g_xl [MROWS*DIMM];
__device__ __align__(16) __nv_bfloat16 g_uh [MROWS*DIMM],  g_ul [MROWS*DIMM];
__device__ __align__(16) __nv_bfloat16 g_qh [MROWS*DIMM],  g_ql [MROWS*DIMM];
__device__ __align__(16) __nv_bfloat16 g_kh [MROWS*DIMM],  g_kl [MROWS*DIMM];
__device__ __align__(16) __nv_bfloat16 g_wqh[QKVDIM*DIMM], g_wql[QKVDIM*DIMM];
__device__ __align__(16) __nv_bfloat16 g_woh[DIMM*DIMM],   g_wol[DIMM*DIMM];
__device__ __align__(16) __nv_bfloat16 g_sqh[NSEQ*DH],     g_sql[NSEQ*DH];   // wq split
__device__ __align__(16) __nv_bfloat16 g_skh[NSEQ*DH],     g_skl[NSEQ*DH];   // wk split

// ============================================================================
// fp32 -> bf16 hi/lo split (x = hi + lo), vectorized 4/thread
// ============================================================================
__device__ __forceinline__ void split4_store(__nv_bfloat16* hi, __nv_bfloat16* lo,
                                             int i, float4 v) {
    __nv_bfloat16 h0 = __float2bfloat16(v.x);
    __nv_bfloat16 h1 = __float2bfloat16(v.y);
    __nv_bfloat16 h2 = __float2bfloat16(v.z);
    __nv_bfloat16 h3 = __float2bfloat16(v.w);
    __nv_bfloat16 l0 = __float2bfloat16(v.x - __bfloat162float(h0));
    __nv_bfloat16 l1 = __float2bfloat16(v.y - __bfloat162float(h1));
    __nv_bfloat16 l2 = __float2bfloat16(v.z - __bfloat162float(h2));
    __nv_bfloat16 l3 = __float2bfloat16(v.w - __bfloat162float(h3));
    uint2 ph, pl;
    ph.x = (uint32_t)__bfloat16_as_ushort(h0) | ((uint32_t)__bfloat16_as_ushort(h1) << 16);
    ph.y = (uint32_t)__bfloat16_as_ushort(h2) | ((uint32_t)__bfloat16_as_ushort(h3) << 16);
    pl.x = (uint32_t)__bfloat16_as_ushort(l0) | ((uint32_t)__bfloat16_as_ushort(l1) << 16);
    pl.y = (uint32_t)__bfloat16_as_ushort(l2) | ((uint32_t)__bfloat16_as_ushort(l3) << 16);
    *(uint2*)(hi + i) = ph;
    *(uint2*)(lo + i) = pl;
}

__global__ __launch_bounds__(256)
void cvt_split(const float* __restrict__ src, __nv_bfloat16* __restrict__ hi,
               __nv_bfloat16* __restrict__ lo, int n)
{
    int i = (blockIdx.x * blockDim.x + threadIdx.x) * 4;
    if (i >= n) return;
    split4_store(hi, lo, i, *(const float4*)(src + i));
}

// u = g2 * v (heads merged), split to bf16 hi/lo
__global__ __launch_bounds__(256)
void cvt_u()
{
    int i = (blockIdx.x * blockDim.x + threadIdx.x) * 4;
    if (i >= MROWS * DIMM) return;
    int row = i >> 9;
    int col = i & (DIMM - 1);
    int bh  = ((row >> 10) << 3) + (col >> 6);
    float g = g_g2[bh * NSEQ + (row & (NSEQ - 1))];
    float4 v = *(const float4*)(g_qkv + (size_t)row * QKVDIM + 2 * DIMM + col);
    v.x *= g; v.y *= g; v.z *= g; v.w *= g;
    split4_store(g_uh, g_ul, i, v);
}

// ============================================================================
// Split-bf16 warp-MMA GEMM. K-chunk 32, THREE-stage cp.async pipeline
// (prefetch depth 2 chunks, ONE __syncthreads per chunk), 1 CTA/SM with
// unconstrained registers. Block tile 128x128, 8 warps (wm: 64 rows, wn: 32).
// QK==1: also emit bf16 hi/lo of q and k sections from the epilogue.
// Pipeline safety: at iter kc we write buf (kc+2)%3, whose previous readers
// (iter kc-1, buf (kc-1)%3 == (kc+2)%3) all passed the iter-kc barrier.
// Wait math: at iter kc, groups issued = kc+2, need group kc -> pending<=1.
// ============================================================================
#define TPAD   40                       // 32 + 8 pad (80B rows, 16B-aligned, conflict-free)
#define PART_B (128 * TPAD * 2)         // 10240 B
#define BUF_B  (PART_B * 4)             // Ah|Al|Bh|Bl = 40960 B
#define GSMEM_TOTAL (BUF_B * 3)         // 122880 B triple-buffered

template <int EPI, int QK>
__global__ __launch_bounds__(256)
void gemm_mma(const __nv_bfloat16* __restrict__ Ah, const __nv_bfloat16* __restrict__ Al,
              const __nv_bfloat16* __restrict__ Bh, const __nv_bfloat16* __restrict__ Bl,
              const float* __restrict__ bias, const float* __restrict__ extra,
              float* __restrict__ C, int Nc, int K)
{
    extern __shared__ char smem[];
    const uint32_t sb = smem_u32(smem);
    const int tid  = threadIdx.x;
    const int lane = tid & 31;
    const int wid  = tid >> 5;
    const int wm   = wid & 1;
    const int wn   = wid >> 1;
    const int bm = blockIdx.y * 128;
    const int bn = blockIdx.x * 128;
    const int nch = K / 32;

    auto issue = [&](int kc, int buf) {
        uint32_t dbase = sb + buf * BUF_B;
#pragma unroll
        for (int p = 0; p < 4; p++) {
            const __nv_bfloat16* s = (p == 0 ? Ah : p == 1 ? Al : p == 2 ? Bh : Bl);
            int rowoff = (p < 2) ? bm : bn;
#pragma unroll
            for (int i = 0; i < 2; i++) {
                int c = tid + i * 256;           // 0..511 16B-chunks
                int r = c >> 2, c8 = (c & 3) * 8;
                const void* g = s + (size_t)(rowoff + r) * K + kc * 32 + c8;
                uint32_t d = dbase + p * PART_B + (r * TPAD + c8) * 2;
                CP_ASYNC16(d, g);
            }
        }
        CP_COMMIT();
    };

    float acc[4][4][4];
#pragma unroll
    for (int mf = 0; mf < 4; mf++)
#pragma unroll
        for (int nf = 0; nf < 4; nf++)
#pragma unroll
            for (int c = 0; c < 4; c++) acc[mf][nf][c] = 0.f;

    issue(0, 0);
    if (nch > 1) issue(1, 1);
    int cur = 0;
    for (int kc = 0; kc < nch; kc++) {
        if (kc + 1 < nch) { CP_WAIT1(); }
        else              { CP_WAIT0(); }
        __syncthreads();
        if (kc + 2 < nch) {
            int nb = cur + 2; if (nb >= 3) nb -= 3;
            issue(kc + 2, nb);
        }

        uint32_t base = sb + cur * BUF_B;
#pragma unroll
        for (int ks = 0; ks < 2; ks++) {
            uint32_t ah[4][4], al[4][4];
#pragma unroll
            for (int mf = 0; mf < 4; mf++) {
                uint32_t ro = (uint32_t)((wm * 64 + mf * 16 + (lane & 15)) * (TPAD * 2)
                             + (ks * 16 + ((lane >> 4) & 1) * 8) * 2);
                ldsm_x4(ah[mf], base + 0 * PART_B + ro);
                ldsm_x4(al[mf], base + 1 * PART_B + ro);
            }
            uint32_t bh[2][4], bl[2][4];
#pragma unroll
            for (int g2i = 0; g2i < 2; g2i++) {
                uint32_t ro = (uint32_t)((wn * 32 + g2i * 16 + (lane & 7) + ((lane >> 4) & 1) * 8) * (TPAD * 2)
                             + (ks * 16 + ((lane >> 3) & 1) * 8) * 2);
                ldsm_x4(bh[g2i], base + 2 * PART_B + ro);
                ldsm_x4(bl[g2i], base + 3 * PART_B + ro);
            }
#pragma unroll
            for (int mf = 0; mf < 4; mf++) {
#pragma unroll
                for (int nf = 0; nf < 4; nf++) {
                    int g2n = nf >> 1, sub = (nf & 1) * 2;
                    uint32_t bh0 = bh[g2n][sub], bh1 = bh[g2n][sub + 1];
                    uint32_t bl0 = bl[g2n][sub], bl1 = bl[g2n][sub + 1];
                    mma_bf16(acc[mf][nf], ah[mf], bh0, bh1);
                    mma_bf16(acc[mf][nf], ah[mf], bl0, bl1);
                    mma_bf16(acc[mf][nf], al[mf], bh0, bh1);
                }
            }
        }
        cur = (cur + 1 == 3) ? 0 : cur + 1;
    }

    const int gr = lane >> 2, qc = (lane & 3) * 2;
#pragma unroll
    for (int mf = 0; mf < 4; mf++) {
#pragma unroll
        for (int h = 0; h < 2; h++) {
            int row = bm + wm * 64 + mf * 16 + gr + h * 8;
#pragma unroll
            for (int nf = 0; nf < 4; nf++) {
                int col = bn + wn * 32 + nf * 8 + qc;
                float2 v;
                v.x = acc[mf][nf][h * 2 + 0] + bias[col];
                v.y = acc[mf][nf][h * 2 + 1] + bias[col + 1];
                if (EPI == 1) {
                    const float* e = extra + (size_t)row * QKVDIM + col;
                    v.x += e[0]; v.y += e[1];
                }
                *(float2*)(C + (size_t)row * Nc + col) = v;
                if (QK == 1 && col < 2 * DIMM) {
                    __nv_bfloat16 h0 = __float2bfloat16(v.x);
                    __nv_bfloat16 h1 = __float2bfloat16(v.y);
                    __nv_bfloat16 l0 = __float2bfloat16(v.x - __bfloat162float(h0));
                    __nv_bfloat16 l1 = __float2bfloat16(v.y - __bfloat162float(h1));
                    uint32_t ph = (uint32_t)__bfloat16_as_ushort(h0)
                                | ((uint32_t)__bfloat16_as_ushort(h1) << 16);
                    uint32_t pl = (uint32_t)__bfloat16_as_ushort(l0)
                                | ((uint32_t)__bfloat16_as_ushort(l1) << 16);
                    if (col < DIMM) {
                        size_t idx = (size_t)row * DIMM + col;
                        *(uint32_t*)(g_qh + idx) = ph;
                        *(uint32_t*)(g_ql + idx) = pl;
                    } else {
                        size_t idx = (size_t)row * DIMM + (col - DIMM);
                        *(uint32_t*)(g_kh + idx) = ph;
                        *(uint32_t*)(g_kl + idx) = pl;
                    }
                }
            }
        }
    }
}

// ============================================================================
// Per-(b,h,n): qsum = sum_d q, ksum = sum_d k. One warp per row.
// ============================================================================
__global__ __launch_bounds__(256)
void sums_kernel()
{
    int warp = (blockIdx.x * blockDim.x + threadIdx.x) >> 5;
    int lane = threadIdx.x & 31;
    if (warp >= BH * NSEQ) return;
    int bh = warp / NSEQ, n = warp % NSEQ;
    int b = bh / HEADS, h = bh % HEADS;
    const float* row = g_qkv + (size_t)(b * NSEQ + n) * QKVDIM + h * DH;
    float q = row[lane] + row[lane + 32];
    float k = row[DIMM + lane] + row[DIMM + lane + 32];
#pragma unroll
    for (int o = 16; o; o >>= 1) {
        q += __shfl_xor_sync(0xFFFFFFFFu, q, o);
        k += __shfl_xor_sync(0xFFFFFFFFu, k, o);
    }
    if (lane == 0) { g_qsum[warp] = q; g_ksum[warp] = k; }
}

// ============================================================================
// Stage kernel on mma.sync (split-bf16) — benched config from R14 (unchanged).
// ============================================================================
#define QTPAD  72
#define SSM_QH   0
#define SSM_QL   9216                       // 64*72*2
#define SSM_W    18432
#define SSM_WPART 18432                     // 128*72*2
#define SSM_WBUF (2 * SSM_WPART)
#define SSM_BIAS (SSM_W + 2 * SSM_WBUF)     // 92160
#define SSM_WV   (SSM_BIAS + 4096)
#define SSM_REDS (SSM_WV + 4096)
#define SSM_REDW (SSM_REDS + 1024)
#define SSM_TOTAL (SSM_REDW + 1024)         // 103424

template <int STAGE>
__global__ __launch_bounds__(256, 2)
void stage_mma(const __nv_bfloat16* __restrict__ Ah, const __nv_bfloat16* __restrict__ Al,
               const __nv_bfloat16* __restrict__ Wh, const __nv_bfloat16* __restrict__ Wl,
               const float* __restrict__ bias, float* __restrict__ gout)
{
    extern __shared__ char smem[];
    const uint32_t sb = smem_u32(smem);
    float* s_bias = (float*)(smem + SSM_BIAS);
    float* s_wv   = (float*)(smem + SSM_WV);
    float* s_reds = (float*)(smem + SSM_REDS);
    float* s_redw = (float*)(smem + SSM_REDW);

    const int bh   = blockIdx.y;
    const int b    = bh >> 3, h = bh & 7;
    const int row0 = blockIdx.x * 64;
    const int tid  = threadIdx.x;
    const int lane = tid & 31;
    const int wid  = tid >> 5;
    const int wm   = wid & 1;
    const int wn   = wid >> 1;
    const int gr   = lane >> 2, qc = (lane & 3) * 2;

    {
#pragma unroll
        for (int i = 0; i < 4; i++) {
            int chunk = tid + i * 256;       // 0..1023
            int part = chunk >> 9, c = chunk & 511;
            int r = c >> 3, c8 = (c & 7) * 8;
            const __nv_bfloat16* s = part ? Al : Ah;
            const void* g = s + (size_t)(b * NSEQ + row0 + r) * DIMM + h * DH + c8;
            uint32_t d = sb + (part ? SSM_QL : SSM_QH) + (r * QTPAD + c8) * 2;
            CP_ASYNC16(d, g);
        }
        CP_COMMIT();
    }
    auto issueW = [&](int jc, int buf) {
#pragma unroll
        for (int i = 0; i < 8; i++) {
            int chunk = tid + i * 256;       // 0..2047
            int part = chunk >> 10, c = chunk & 1023;
            int r = c >> 3, c8 = (c & 7) * 8;
            const __nv_bfloat16* s = part ? Wl : Wh;
            const void* g = s + (size_t)(jc * 128 + r) * DH + c8;
            uint32_t d = sb + SSM_W + buf * SSM_WBUF + part * SSM_WPART + (r * QTPAD + c8) * 2;
            CP_ASYNC16(d, g);
        }
        CP_COMMIT();
    };
    issueW(0, 0);

#pragma unroll
    for (int i = 0; i < 4; i++) {
        int c = tid * 4 + i;
        s_bias[c] = bias[c] * ATT_SCALE;
        if (STAGE == 0) s_wv[c] = g_qsum[bh * NSEQ + c];
        else            s_wv[c] = g_g1[bh * NSEQ + c] * g_ksum[bh * NSEQ + c];
    }
    float rsc[2][2];
#pragma unroll
    for (int mf = 0; mf < 2; mf++)
#pragma unroll
        for (int hh = 0; hh < 2; hh++) {
            int row = row0 + wm * 32 + mf * 16 + gr + hh * 8;
            rsc[mf][hh] = (STAGE == 1) ? g_g1[bh * NSEQ + row] * ATT_SCALE : ATT_SCALE;
        }

    float Sx[2][2] = {{0.f,0.f},{0.f,0.f}};
    float Wx[2][2] = {{0.f,0.f},{0.f,0.f}};

    for (int jc = 0; jc < 8; jc++) {
        if (jc + 1 < 8) { issueW(jc + 1, (jc + 1) & 1); CP_WAIT1(); }
        else            { CP_WAIT0(); }
        __syncthreads();

        uint32_t wbase = sb + SSM_W + (jc & 1) * SSM_WBUF;
        float acc[2][4][4];
#pragma unroll
        for (int mf = 0; mf < 2; mf++)
#pragma unroll
            for (int nf = 0; nf < 4; nf++)
#pragma unroll
                for (int c = 0; c < 4; c++) acc[mf][nf][c] = 0.f;

#pragma unroll
        for (int ks = 0; ks < 4; ks++) {
            uint32_t ah[2][4], al[2][4];
#pragma unroll
            for (int mf = 0; mf < 2; mf++) {
                uint32_t ro = (uint32_t)((wm * 32 + mf * 16 + (lane & 15)) * (QTPAD * 2)
                             + (ks * 16 + ((lane >> 4) & 1) * 8) * 2);
                ldsm_x4(ah[mf], sb + SSM_QH + ro);
                ldsm_x4(al[mf], sb + SSM_QL + ro);
            }
            uint32_t bh_[2][4], bl_[2][4];
#pragma unroll
            for (int g2i = 0; g2i < 2; g2i++) {
                uint32_t ro = (uint32_t)((wn * 32 + g2i * 16 + (lane & 7) + ((lane >> 4) & 1) * 8) * (QTPAD * 2)
                             + (ks * 16 + ((lane >> 3) & 1) * 8) * 2);
                ldsm_x4(bh_[g2i], wbase + 0 * SSM_WPART + ro);
                ldsm_x4(bl_[g2i], wbase + 1 * SSM_WPART + ro);
            }
#pragma unroll
            for (int mf = 0; mf < 2; mf++) {
#pragma unroll
                for (int nf = 0; nf < 4; nf++) {
                    int g2n = nf >> 1, sub = (nf & 1) * 2;
                    uint32_t b0h = bh_[g2n][sub], b1h = bh_[g2n][sub + 1];
                    uint32_t b0l = bl_[g2n][sub], b1l = bl_[g2n][sub + 1];
                    mma_bf16(acc[mf][nf], ah[mf], b0h, b1h);
                    mma_bf16(acc[mf][nf], ah[mf], b0l, b1l);
                    mma_bf16(acc[mf][nf], al[mf], b0h, b1h);
                }
            }
        }

#pragma unroll
        for (int mf = 0; mf < 2; mf++) {
#pragma unroll
            for (int nf = 0; nf < 4; nf++) {
                int col = jc * 128 + wn * 32 + nf * 8 + qc;
                float b0 = s_bias[col], b1 = s_bias[col + 1];
                float v0 = s_wv[col],   v1 = s_wv[col + 1];
#pragma unroll
                for (int hh = 0; hh < 2; hh++) {
                    float e0 = __expf(fmaf(acc[mf][nf][hh * 2 + 0], rsc[mf][hh], b0));
                    float e1 = __expf(fmaf(acc[mf][nf][hh * 2 + 1], rsc[mf][hh], b1));
                    Sx[mf][hh] += e0 + e1;
                    Wx[mf][hh] += e0 * v0 + e1 * v1;
                }
            }
        }
        __syncthreads();
    }

#pragma unroll
    for (int mf = 0; mf < 2; mf++)
#pragma unroll
        for (int hh = 0; hh < 2; hh++) {
#pragma unroll
            for (int o = 2; o; o >>= 1) {
                Sx[mf][hh] += __shfl_xor_sync(0xFFFFFFFFu, Sx[mf][hh], o);
                Wx[mf][hh] += __shfl_xor_sync(0xFFFFFFFFu, Wx[mf][hh], o);
            }
        }
    if ((lane & 3) == 0) {
#pragma unroll
        for (int mf = 0; mf < 2; mf++)
#pragma unroll
            for (int hh = 0; hh < 2; hh++) {
                int lr = wm * 32 + mf * 16 + hh * 8 + gr;
                s_reds[wn * 64 + lr] = Sx[mf][hh];
                s_redw[wn * 64 + lr] = Wx[mf][hh];
            }
    }
    __syncthreads();
    if (tid < 64) {
        float S = s_reds[tid] + s_reds[64 + tid] + s_reds[128 + tid] + s_reds[192 + tid];
        float W = s_redw[tid] + s_redw[64 + tid] + s_redw[128 + tid] + s_redw[192 + tid];
        gout[bh * NSEQ + row0 + tid] = W / S;
    }
}

// ============================================================================
// launch
// ============================================================================
extern "C" void kernel_launch(void* const* d_in, const int* in_sizes, int n_in,
                              void* d_out, int out_size)
{
    const float* x     = (const float*)d_in[0];
    const float* w_qkv = (const float*)d_in[1];
    const float* b_qkv = (const float*)d_in[2];
    const float* wq    = (const float*)d_in[3];
    const float* bq    = (const float*)d_in[4];
    const float* wk    = (const float*)d_in[5];
    const float* bk    = (const float*)d_in[6];
    const float* w_out = (const float*)d_in[7];
    const float* b_out = (const float*)d_in[8];
    float* out = (float*)d_out;

    float *p_qkv, *p_g1, *p_g2;
    cudaGetSymbolAddress((void**)&p_qkv, g_qkv);
    cudaGetSymbolAddress((void**)&p_g1,  g_g1);
    cudaGetSymbolAddress((void**)&p_g2,  g_g2);
    __nv_bfloat16 *xh, *xl, *uh, *ul, *wqh, *wql, *woh, *wol;
    __nv_bfloat16 *qh, *ql, *kh, *kl, *sqh, *sql, *skh, *skl;
    cudaGetSymbolAddress((void**)&xh,  g_xh);  cudaGetSymbolAddress((void**)&xl,  g_xl);
    cudaGetSymbolAddress((void**)&uh,  g_uh);  cudaGetSymbolAddress((void**)&ul,  g_ul);
    cudaGetSymbolAddress((void**)&wqh, g_wqh); cudaGetSymbolAddress((void**)&wql, g_wql);
    cudaGetSymbolAddress((void**)&woh, g_woh); cudaGetSymbolAddress((void**)&wol, g_wol);
    cudaGetSymbolAddress((void**)&qh,  g_qh);  cudaGetSymbolAddress((void**)&ql,  g_ql);
    cudaGetSymbolAddress((void**)&kh,  g_kh);  cudaGetSymbolAddress((void**)&kl,  g_kl);
    cudaGetSymbolAddress((void**)&sqh, g_sqh); cudaGetSymbolAddress((void**)&sql, g_sql);
    cudaGetSymbolAddress((void**)&skh, g_skh); cudaGetSymbolAddress((void**)&skl, g_skl);

    cudaFuncSetAttribute(gemm_mma<0,1>, cudaFuncAttributeMaxDynamicSharedMemorySize, GSMEM_TOTAL);
    cudaFuncSetAttribute(gemm_mma<1,0>, cudaFuncAttributeMaxDynamicSharedMemorySize, GSMEM_TOTAL);
    cudaFuncSetAttribute(stage_mma<0>, cudaFuncAttributeMaxDynamicSharedMemorySize, SSM_TOTAL);
    cudaFuncSetAttribute(stage_mma<1>, cudaFuncAttributeMaxDynamicSharedMemorySize, SSM_TOTAL);

    // 0) pre-convert operands to bf16 hi/lo
    cvt_split<<<(MROWS*DIMM/4 + 255)/256, 256>>>(x, xh, xl, MROWS*DIMM);
    cvt_split<<<(QKVDIM*DIMM/4 + 255)/256, 256>>>(w_qkv, wqh, wql, QKVDIM*DIMM);
    cvt_split<<<(DIMM*DIMM/4 + 255)/256, 256>>>(w_out, woh, wol, DIMM*DIMM);
    cvt_split<<<(NSEQ*DH/4 + 255)/256, 256>>>(wq, sqh, sql, NSEQ*DH);
    cvt_split<<<(NSEQ*DH/4 + 255)/256, 256>>>(wk, skh, skl, NSEQ*DH);

    // 1) qkv = x @ w_qkv^T + b_qkv  (also emits q/k bf16 hi/lo from epilogue)
    gemm_mma<0,1><<<dim3(QKVDIM/128, MROWS/128), 256, GSMEM_TOTAL>>>(
        xh, xl, wqh, wql, b_qkv, nullptr, p_qkv, QKVDIM, DIMM);

    // 2) row sums of q and k per head
    sums_kernel<<<(BH*NSEQ*32)/256, 256>>>();

    // 3) stage 1 -> g1 ; 4) stage 2 -> g2   (warp-MMA)
    stage_mma<0><<<dim3(NSEQ/64, BH), 256, SSM_TOTAL>>>(qh, ql, sqh, sql, bq, p_g1);
    stage_mma<1><<<dim3(NSEQ/64, BH), 256, SSM_TOTAL>>>(kh, kl, skh, skl, bk, p_g2);

    // 5) u = g2 * v, split to bf16
    cvt_u<<<(MROWS*DIMM/4 + 255)/256, 256>>>();

    // 6) out = u @ w_out^T + b_out + qo   (warp-MMA)
    gemm_mma<1,0><<<dim3(DIMM/128, MROWS/128), 256, GSMEM_TOTAL>>>(
        uh, ul, woh, wol, b_out, p_qkv, out, DIMM, DIMM);
}